// round 2
// baseline (speedup 1.0000x reference)
#include <cuda_runtime.h>

#define BATCH 1024
#define VOCAB 50000
#define DIM   300

#define BM 64          // rows per block tile
#define BN 320         // padded cols (covers DIM=300)
#define VK 16          // k-slice per smem tile
#define TM 4           // rows per thread
#define TNV 10         // float2 cols per thread (20 scalar cols)
#define SPLITS 18      // split-K segments
#define SEG 2778       // ceil(VOCAB / SPLITS)

// split-K partials: [SPLITS][BATCH][DIM]  (22.1 MB, static scratch — no allocs)
__device__ float g_partial[(size_t)SPLITS * BATCH * DIM];

__global__ __launch_bounds__(256) void gemm_splitk_kernel(
    const float* __restrict__ labels,   // (BATCH, VOCAB)
    const float* __restrict__ weight)   // (VOCAB, DIM)
{
    __shared__ float sA[BM][VK];        // labels tile
    __shared__ float sB[VK][BN];        // weight tile (cols >= DIM zero-filled)

    const int tid = threadIdx.x;
    const int tx = tid & 15;            // 0..15 -> col group (20 cols each)
    const int ty = tid >> 4;            // 0..15 -> row group (4 rows each)
    const int row0 = blockIdx.x * BM;
    const int s = blockIdx.y;
    const int k_start = s * SEG;
    const int k_end = min(VOCAB, k_start + SEG);

    unsigned long long acc[TM][TNV];
#pragma unroll
    for (int i = 0; i < TM; i++)
#pragma unroll
        for (int j = 0; j < TNV; j++)
            acc[i][j] = 0ull;   // packed (0.f, 0.f)

    for (int k0 = k_start; k0 < k_end; k0 += VK) {
        // ---- load A tile: 64 rows x 16 k, 4 scalars per thread ----
        {
            const int r  = tid >> 2;          // 0..63
            const int kk = (tid & 3) * 4;     // 0,4,8,12
            const float* src = labels + (size_t)(row0 + r) * VOCAB + k0 + kk;
#pragma unroll
            for (int i = 0; i < 4; i++) {
                const int kg = k0 + kk + i;
                sA[r][kk + i] = (kg < k_end) ? src[i] : 0.f;
            }
        }
        // ---- load B tile: 16 k x 320 cols, 20 scalars per thread ----
#pragma unroll
        for (int i = 0; i < 20; i++) {
            const int idx = i * 256 + tid;
            const int r = idx / BN;
            const int c = idx - r * BN;
            const int kg = k0 + r;
            sB[r][c] = (kg < k_end && c < DIM) ? weight[(size_t)kg * DIM + c] : 0.f;
        }
        __syncthreads();

        // ---- compute: 16 k-steps x (4x10) fma.rn.f32x2 ----
#pragma unroll
        for (int k = 0; k < VK; k++) {
            unsigned long long bv[TNV];
#pragma unroll
            for (int j = 0; j < TNV; j++)
                bv[j] = *reinterpret_cast<const unsigned long long*>(
                            &sB[k][tx * 20 + j * 2]);
#pragma unroll
            for (int i = 0; i < TM; i++) {
                const float a = sA[ty * TM + i][k];
                unsigned long long av;
                asm("mov.b64 %0, {%1, %1};" : "=l"(av) : "f"(a));
#pragma unroll
                for (int j = 0; j < TNV; j++)
                    asm("fma.rn.f32x2 %0, %1, %2, %0;"
                        : "+l"(acc[i][j]) : "l"(av), "l"(bv[j]));
            }
        }
        __syncthreads();
    }

    // ---- epilogue: write partials (only cols < DIM) ----
    float* outp = g_partial + (size_t)s * BATCH * DIM;
#pragma unroll
    for (int i = 0; i < TM; i++) {
        const int row = row0 + ty * TM + i;
#pragma unroll
        for (int j = 0; j < TNV; j++) {
            float lo, hi;
            asm("mov.b64 {%0, %1}, %2;" : "=f"(lo), "=f"(hi) : "l"(acc[i][j]));
            const int c = tx * 20 + j * 2;
            if (c < DIM)     outp[(size_t)row * DIM + c]     = lo;
            if (c + 1 < DIM) outp[(size_t)row * DIM + c + 1] = hi;
        }
    }
}

__global__ __launch_bounds__(512) void reduce_norm_kernel(float* __restrict__ out)
{
    __shared__ float sred[512];
    const int b = blockIdx.x;
    const int tid = threadIdx.x;

    float attr = 0.f;
    if (tid < DIM) {
#pragma unroll
        for (int s = 0; s < SPLITS; s++)
            attr += g_partial[((size_t)s * BATCH + b) * DIM + tid];
    }
    sred[tid] = attr * attr;
    __syncthreads();
#pragma unroll
    for (int off = 256; off > 0; off >>= 1) {
        if (tid < off) sred[tid] += sred[tid + off];
        __syncthreads();
    }
    const float inv = 1.f / (sqrtf(sred[0]) + 1e-7f);
    if (tid < DIM) out[(size_t)b * DIM + tid] = attr * inv;
}

extern "C" void kernel_launch(void* const* d_in, const int* in_sizes, int n_in,
                              void* d_out, int out_size)
{
    const float* labels = (const float*)d_in[0];   // (1024, 50000)
    const float* weight = (const float*)d_in[1];   // (50000, 300)
    float* out = (float*)d_out;                    // (1024, 300)

    dim3 grid(BATCH / BM, SPLITS);
    gemm_splitk_kernel<<<grid, 256>>>(labels, weight);
    reduce_norm_kernel<<<BATCH, 512>>>(out);
}

// round 4
// speedup vs baseline: 2.8368x; 2.8368x over previous
#include <cuda_runtime.h>
#include <cuda_bf16.h>
#include <cstdint>

#define BATCH 1024
#define VOCAB 50000
#define DIM   300

#define BM      64
#define BN      320
#define KC      32
#define SPLITS  9
#define SEG     5568            // SPLITS*SEG = 50112 >= VOCAB, mult of KC
#define K_PAD   50112
#define NCHUNK  (SEG / KC)      // 174

// -------- static device scratch (no allocations allowed) --------
__device__ __nv_bfloat16 g_bhi[(size_t)BN * K_PAD];   // weight hi, [n][k] (col-major B)
__device__ __nv_bfloat16 g_blo[(size_t)BN * K_PAD];   // weight lo, [n][k]
__device__ float g_partial[(size_t)SPLITS * BATCH * DIM];

// smem region offsets (bytes). Row stride 40 bf16 = 80B (conflict-free frags).
#define A_STRIDE 80
#define A_BYTES  (64 * A_STRIDE)        // 5120
#define B_BYTES  (320 * A_STRIDE)       // 25600
#define BUF_BYTES (2 * A_BYTES + 2 * B_BYTES)   // 61440
#define A_HI(b) ((b) * BUF_BYTES + 0)
#define A_LO(b) ((b) * BUF_BYTES + A_BYTES)
#define B_HI(b) ((b) * BUF_BYTES + 2 * A_BYTES)
#define B_LO(b) ((b) * BUF_BYTES + 2 * A_BYTES + B_BYTES)
#define SMEM_TOTAL (2 * BUF_BYTES)      // 122880

__device__ __forceinline__ uint32_t smem_u32(const void* p) {
    uint32_t a;
    asm("{ .reg .u64 t; cvta.to.shared.u64 t, %1; cvt.u32.u64 %0, t; }"
        : "=r"(a) : "l"(p));
    return a;
}
__device__ __forceinline__ void cp_async16(uint32_t dst, const void* src) {
    asm volatile("{ .reg .u64 g; cvta.to.global.u64 g, %1; "
                 "cp.async.ca.shared.global [%0], [g], 16; }"
                 :: "r"(dst), "l"(src) : "memory");
}
#define CP_COMMIT() asm volatile("cp.async.commit_group;" ::: "memory")
#define CP_WAIT0()  asm volatile("cp.async.wait_group 0;" ::: "memory")

__device__ __forceinline__ void mma16816(float* d, const uint32_t* a,
                                         uint32_t b0, uint32_t b1) {
    asm volatile("mma.sync.aligned.m16n8k16.row.col.f32.bf16.bf16.f32 "
                 "{%0,%1,%2,%3}, {%4,%5,%6,%7}, {%8,%9}, {%0,%1,%2,%3};"
                 : "+f"(d[0]), "+f"(d[1]), "+f"(d[2]), "+f"(d[3])
                 : "r"(a[0]), "r"(a[1]), "r"(a[2]), "r"(a[3]), "r"(b0), "r"(b1));
}

// split (x,y) into packed bf16x2 hi + lo (low half = x)
__device__ __forceinline__ void cvt_split2(float x, float y, uint32_t& h, uint32_t& l) {
    uint32_t hh;
    asm("cvt.rn.bf16x2.f32 %0, %1, %2;" : "=r"(hh) : "f"(y), "f"(x));
    float hx = __uint_as_float(hh << 16);
    float hy = __uint_as_float(hh & 0xFFFF0000u);
    float lx = x - hx, ly = y - hy;
    asm("cvt.rn.bf16x2.f32 %0, %1, %2;" : "=r"(l) : "f"(ly), "f"(lx));
    h = hh;
}

// ---------------- prep: weight f32 [K][300] -> bf16 hi/lo [320][K_PAD] ----------------
__global__ __launch_bounds__(256) void prep_kernel(const float* __restrict__ weight)
{
    __shared__ float t[32][33];
    const int k0 = blockIdx.x * 32;
    const int n0 = blockIdx.y * 32;
    const int tx = threadIdx.x;          // 0..31
    const int ty = threadIdx.y;          // 0..7
#pragma unroll
    for (int i = 0; i < 4; i++) {
        const int k = k0 + ty + i * 8;
        const int n = n0 + tx;
        t[ty + i * 8][tx] = (k < VOCAB && n < DIM) ? weight[(size_t)k * DIM + n] : 0.f;
    }
    __syncthreads();
#pragma unroll
    for (int i = 0; i < 4; i++) {
        const int n = n0 + ty + i * 8;
        const int k = k0 + tx;
        const float v = t[tx][ty + i * 8];
        const __nv_bfloat16 hi = __float2bfloat16_rn(v);
        const __nv_bfloat16 lo = __float2bfloat16_rn(v - __bfloat162float(hi));
        g_bhi[(size_t)n * K_PAD + k] = hi;
        g_blo[(size_t)n * K_PAD + k] = lo;
    }
}

// ---------------- GEMM: HMMA bf16 3-term split, split-K ----------------
__global__ __launch_bounds__(256, 1) void gemm_kernel(const float* __restrict__ labels)
{
    extern __shared__ char smem[];
    const uint32_t smem_base = smem_u32(smem);

    const int tid = threadIdx.x;
    const int wid = tid >> 5;
    const int lane = tid & 31;
    const int lr = lane >> 2;            // 0..7
    const int lc = lane & 3;             // 0..3
    const int warp_m = wid & 1;          // 2 m-warps (32 rows each)
    const int warp_n = wid >> 1;         // 4 n-warps (80 cols each)

    const int row0 = blockIdx.x * BM;
    const int s = blockIdx.y;
    const int k_start = s * SEG;

    // A f32 staging indices
    const int arow = tid >> 3;           // 0..31 (rows r and r+32)
    const int af4 = tid & 7;             // float4 col 0..7 (k = af4*4..af4*4+3)

    float acc[2][10][4];
#pragma unroll
    for (int mt = 0; mt < 2; mt++)
#pragma unroll
        for (int nt = 0; nt < 10; nt++)
#pragma unroll
            for (int i = 0; i < 4; i++) acc[mt][nt][i] = 0.f;

    // ---- helpers as lambdas ----
    auto loadA = [&](int kc0, float4* v) {
#pragma unroll
        for (int i = 0; i < 2; i++) {
            const int r = row0 + arow + i * 32;
            const int k = kc0 + af4 * 4;
            const float* src = labels + (size_t)r * VOCAB + k;
            if (k + 3 < VOCAB) {
                v[i] = *reinterpret_cast<const float4*>(src);
            } else {
                v[i].x = (k     < VOCAB) ? src[0] : 0.f;
                v[i].y = (k + 1 < VOCAB) ? src[1] : 0.f;
                v[i].z = (k + 2 < VOCAB) ? src[2] : 0.f;
                v[i].w = (k + 3 < VOCAB) ? src[3] : 0.f;
            }
        }
    };
    auto stsA = [&](int buf, const float4* v) {
#pragma unroll
        for (int i = 0; i < 2; i++) {
            uint32_t h0, l0, h1, l1;
            cvt_split2(v[i].x, v[i].y, h0, l0);
            cvt_split2(v[i].z, v[i].w, h1, l1);
            const int off = (arow + i * 32) * A_STRIDE + af4 * 8;
            *reinterpret_cast<uint32_t*>(smem + A_HI(buf) + off)     = h0;
            *reinterpret_cast<uint32_t*>(smem + A_HI(buf) + off + 4) = h1;
            *reinterpret_cast<uint32_t*>(smem + A_LO(buf) + off)     = l0;
            *reinterpret_cast<uint32_t*>(smem + A_LO(buf) + off + 4) = l1;
        }
    };
    auto loadB = [&](int kc0, int buf) {
#pragma unroll
        for (int i = 0; i < 5; i++) {
            const int idx = tid + 256 * i;     // 0..1279
            const int n = idx >> 2;
            const int seg = idx & 3;
            const int doff = n * A_STRIDE + seg * 16;
            const size_t goff = (size_t)n * K_PAD + kc0 + seg * 8;
            cp_async16(smem_base + B_HI(buf) + doff, g_bhi + goff);
            cp_async16(smem_base + B_LO(buf) + doff, g_blo + goff);
        }
        CP_COMMIT();
    };
    auto compute = [&](int buf) {
        const int abase_hi = A_HI(buf) + (warp_m * 32 + lr) * A_STRIDE + lc * 4;
        const int bbase_hi = B_HI(buf) + (warp_n * 80 + lr) * A_STRIDE + lc * 4;
#pragma unroll
        for (int kk = 0; kk < 2; kk++) {
            uint32_t ah[2][4], al[2][4];
#pragma unroll
            for (int mt = 0; mt < 2; mt++) {
                const int a0 = abase_hi + mt * 16 * A_STRIDE + kk * 32;
                ah[mt][0] = *reinterpret_cast<const uint32_t*>(smem + a0);
                ah[mt][1] = *reinterpret_cast<const uint32_t*>(smem + a0 + 8 * A_STRIDE);
                ah[mt][2] = *reinterpret_cast<const uint32_t*>(smem + a0 + 16);
                ah[mt][3] = *reinterpret_cast<const uint32_t*>(smem + a0 + 8 * A_STRIDE + 16);
                const int a1 = a0 + A_BYTES;   // lo region
                al[mt][0] = *reinterpret_cast<const uint32_t*>(smem + a1);
                al[mt][1] = *reinterpret_cast<const uint32_t*>(smem + a1 + 8 * A_STRIDE);
                al[mt][2] = *reinterpret_cast<const uint32_t*>(smem + a1 + 16);
                al[mt][3] = *reinterpret_cast<const uint32_t*>(smem + a1 + 8 * A_STRIDE + 16);
            }
#pragma unroll
            for (int nt = 0; nt < 10; nt++) {
                const int b0 = bbase_hi + nt * 8 * A_STRIDE + kk * 32;
                const uint32_t bh0 = *reinterpret_cast<const uint32_t*>(smem + b0);
                const uint32_t bh1 = *reinterpret_cast<const uint32_t*>(smem + b0 + 16);
                const int b1 = b0 + B_BYTES;   // lo region
                const uint32_t bl0 = *reinterpret_cast<const uint32_t*>(smem + b1);
                const uint32_t bl1 = *reinterpret_cast<const uint32_t*>(smem + b1 + 16);
#pragma unroll
                for (int mt = 0; mt < 2; mt++) {
                    mma16816(acc[mt][nt], ah[mt], bh0, bh1);   // hi*hi
                    mma16816(acc[mt][nt], ah[mt], bl0, bl1);   // hi*lo
                    mma16816(acc[mt][nt], al[mt], bh0, bh1);   // lo*hi
                }
            }
        }
    };

    // ---- prologue: stage chunk 0 ----
    {
        float4 v[2];
        loadA(k_start, v);
        loadB(k_start, 0);
        stsA(0, v);
        CP_WAIT0();
        __syncthreads();
    }

    // ---- main loop ----
    for (int c = 0; c < NCHUNK; c++) {
        const int buf = c & 1;
        const bool has_next = (c + 1 < NCHUNK);
        if (has_next) {
            float4 v[2];
            loadA(k_start + (c + 1) * KC, v);
            loadB(k_start + (c + 1) * KC, buf ^ 1);
            stsA(buf ^ 1, v);
        }
        compute(buf);
        if (has_next) CP_WAIT0();
        __syncthreads();
    }

    // ---- epilogue: write split-K partials ----
    float* outp = g_partial + (size_t)s * BATCH * DIM;
#pragma unroll
    for (int mt = 0; mt < 2; mt++) {
        const int rbase = row0 + warp_m * 32 + mt * 16 + lr;
#pragma unroll
        for (int nt = 0; nt < 10; nt++) {
            const int col = warp_n * 80 + nt * 8 + 2 * lc;
            if (col < DIM) {
                outp[(size_t)rbase * DIM + col] = acc[mt][nt][0];
                if (col + 1 < DIM) outp[(size_t)rbase * DIM + col + 1] = acc[mt][nt][1];
                outp[(size_t)(rbase + 8) * DIM + col] = acc[mt][nt][2];
                if (col + 1 < DIM) outp[(size_t)(rbase + 8) * DIM + col + 1] = acc[mt][nt][3];
            }
        }
    }
}

// ---------------- reduce + L2 normalize ----------------
__global__ __launch_bounds__(512) void reduce_norm_kernel(float* __restrict__ out)
{
    __shared__ float sred[512];
    const int b = blockIdx.x;
    const int tid = threadIdx.x;

    float attr = 0.f;
    if (tid < DIM) {
#pragma unroll
        for (int s = 0; s < SPLITS; s++)
            attr += g_partial[((size_t)s * BATCH + b) * DIM + tid];
    }
    sred[tid] = attr * attr;
    __syncthreads();
#pragma unroll
    for (int off = 256; off > 0; off >>= 1) {
        if (tid < off) sred[tid] += sred[tid + off];
        __syncthreads();
    }
    const float inv = 1.f / (sqrtf(sred[0]) + 1e-7f);
    if (tid < DIM) out[(size_t)b * DIM + tid] = attr * inv;
}

extern "C" void kernel_launch(void* const* d_in, const int* in_sizes, int n_in,
                              void* d_out, int out_size)
{
    const float* labels = (const float*)d_in[0];   // (1024, 50000)
    const float* weight = (const float*)d_in[1];   // (50000, 300)
    float* out = (float*)d_out;                    // (1024, 300)

    cudaFuncSetAttribute(gemm_kernel, cudaFuncAttributeMaxDynamicSharedMemorySize,
                         SMEM_TOTAL);

    prep_kernel<<<dim3(K_PAD / 32, BN / 32), dim3(32, 8)>>>(weight);
    gemm_kernel<<<dim3(BATCH / BM, SPLITS), 256, SMEM_TOTAL>>>(labels);
    reduce_norm_kernel<<<BATCH, 512>>>(out);
}

// round 8
// speedup vs baseline: 3.2886x; 1.1593x over previous
#include <cuda_runtime.h>
#include <cuda_bf16.h>
#include <cstdint>

#define BATCH 1024
#define VOCAB 50000
#define DIM   300

#define BM      64
#define BN      320
#define KC      32
#define SPLITS  9
#define SEG     5568            // SPLITS*SEG = 50112 >= VOCAB, mult of KC
#define K_PAD   50112
#define NCHUNK  (SEG / KC)      // 174

// -------- static device scratch (no allocations allowed) --------
__device__ __nv_bfloat16 g_bhi[(size_t)BN * K_PAD];   // weight hi, [n][k] (col-major B)
__device__ __nv_bfloat16 g_blo[(size_t)BN * K_PAD];   // weight lo, [n][k]
__device__ float g_partial[(size_t)SPLITS * BATCH * DIM];

// smem region offsets (bytes). Row stride 40 bf16 = 80B (conflict-free frags).
#define A_STRIDE 80
#define A_BYTES  (64 * A_STRIDE)        // 5120
#define B_BYTES  (320 * A_STRIDE)       // 25600
#define BUF_BYTES (2 * A_BYTES + 2 * B_BYTES)   // 61440
#define A_HI(b) ((b) * BUF_BYTES + 0)
#define A_LO(b) ((b) * BUF_BYTES + A_BYTES)
#define B_HI(b) ((b) * BUF_BYTES + 2 * A_BYTES)
#define B_LO(b) ((b) * BUF_BYTES + 2 * A_BYTES + B_BYTES)
#define SMEM_TOTAL (2 * BUF_BYTES)      // 122880

__device__ __forceinline__ uint32_t smem_u32(const void* p) {
    uint32_t a;
    asm("{ .reg .u64 t; cvta.to.shared.u64 t, %1; cvt.u32.u64 %0, t; }"
        : "=r"(a) : "l"(p));
    return a;
}
__device__ __forceinline__ void cp_async16(uint32_t dst, const void* src) {
    asm volatile("{ .reg .u64 g; cvta.to.global.u64 g, %1; "
                 "cp.async.ca.shared.global [%0], [g], 16; }"
                 :: "r"(dst), "l"(src) : "memory");
}
#define CP_COMMIT() asm volatile("cp.async.commit_group;" ::: "memory")
#define CP_WAIT0()  asm volatile("cp.async.wait_group 0;" ::: "memory")

__device__ __forceinline__ void mma16816(float* d, const uint32_t* a,
                                         uint32_t b0, uint32_t b1) {
    asm volatile("mma.sync.aligned.m16n8k16.row.col.f32.bf16.bf16.f32 "
                 "{%0,%1,%2,%3}, {%4,%5,%6,%7}, {%8,%9}, {%0,%1,%2,%3};"
                 : "+f"(d[0]), "+f"(d[1]), "+f"(d[2]), "+f"(d[3])
                 : "r"(a[0]), "r"(a[1]), "r"(a[2]), "r"(a[3]), "r"(b0), "r"(b1));
}

// split (x,y) into packed bf16x2 hi + lo (low half = x)
__device__ __forceinline__ void cvt_split2(float x, float y, uint32_t& h, uint32_t& l) {
    uint32_t hh;
    asm("cvt.rn.bf16x2.f32 %0, %1, %2;" : "=r"(hh) : "f"(y), "f"(x));
    float hx = __uint_as_float(hh << 16);
    float hy = __uint_as_float(hh & 0xFFFF0000u);
    float lx = x - hx, ly = y - hy;
    asm("cvt.rn.bf16x2.f32 %0, %1, %2;" : "=r"(l) : "f"(ly), "f"(lx));
    h = hh;
}

// ---------------- prep: weight f32 [K][300] -> bf16 hi/lo [320][K_PAD] ----------------
__global__ __launch_bounds__(256) void prep_kernel(const float* __restrict__ weight)
{
    __shared__ float t[32][33];
    const int k0 = blockIdx.x * 32;
    const int n0 = blockIdx.y * 32;
    const int tx = threadIdx.x & 31;
    const int ty = threadIdx.x >> 5;     // 0..7
#pragma unroll
    for (int i = 0; i < 4; i++) {
        const int k = k0 + ty + i * 8;
        const int n = n0 + tx;
        t[ty + i * 8][tx] = (k < VOCAB && n < DIM) ? weight[(size_t)k * DIM + n] : 0.f;
    }
    __syncthreads();
    // write: thread -> (n_local = tid>>3, k group = (tid&7)*4), 4 consecutive k
    const int nl = threadIdx.x >> 3;
    const int kg = (threadIdx.x & 7) * 4;
    __nv_bfloat16 harr[4], larr[4];
#pragma unroll
    for (int j = 0; j < 4; j++) {
        const float v = t[kg + j][nl];
        const __nv_bfloat16 h = __float2bfloat16_rn(v);
        harr[j] = h;
        larr[j] = __float2bfloat16_rn(v - __bfloat162float(h));
    }
    const size_t off = (size_t)(n0 + nl) * K_PAD + k0 + kg;
    *reinterpret_cast<uint2*>(g_bhi + off) = *reinterpret_cast<uint2*>(harr);
    *reinterpret_cast<uint2*>(g_blo + off) = *reinterpret_cast<uint2*>(larr);
}

// ---------------- GEMM: HMMA bf16 3-term split, split-K ----------------
__global__ __launch_bounds__(256, 1) void gemm_kernel(const float* __restrict__ labels)
{
    extern __shared__ char smem[];
    const uint32_t smem_base = smem_u32(smem);

    const int tid = threadIdx.x;
    const int wid = tid >> 5;
    const int lane = tid & 31;
    const int lr = lane >> 2;            // 0..7
    const int lc = lane & 3;             // 0..3
    const int warp_m = wid & 1;          // 2 m-warps (32 rows each)
    const int warp_n = wid >> 1;         // 4 n-warps (80 cols each)

    const int row0 = blockIdx.x * BM;
    const int s = blockIdx.y;
    const int k_start = s * SEG;

    // A f32 staging indices
    const int arow = tid >> 3;           // 0..31 (rows r and r+32)
    const int af4 = tid & 7;             // float4 col 0..7

    float acc[2][10][4];
#pragma unroll
    for (int mt = 0; mt < 2; mt++)
#pragma unroll
        for (int nt = 0; nt < 10; nt++)
#pragma unroll
            for (int i = 0; i < 4; i++) acc[mt][nt][i] = 0.f;

    auto loadA = [&](int kc0, float4* v) {
#pragma unroll
        for (int i = 0; i < 2; i++) {
            const int r = row0 + arow + i * 32;
            const int k = kc0 + af4 * 4;
            const float* src = labels + (size_t)r * VOCAB + k;
            if (k + 3 < VOCAB) {
                v[i] = *reinterpret_cast<const float4*>(src);
            } else {
                v[i].x = (k     < VOCAB) ? src[0] : 0.f;
                v[i].y = (k + 1 < VOCAB) ? src[1] : 0.f;
                v[i].z = (k + 2 < VOCAB) ? src[2] : 0.f;
                v[i].w = (k + 3 < VOCAB) ? src[3] : 0.f;
            }
        }
    };
    auto stsA = [&](int buf, const float4* v) {
#pragma unroll
        for (int i = 0; i < 2; i++) {
            uint32_t h0, l0, h1, l1;
            cvt_split2(v[i].x, v[i].y, h0, l0);
            cvt_split2(v[i].z, v[i].w, h1, l1);
            const int off = (arow + i * 32) * A_STRIDE + af4 * 8;
            *reinterpret_cast<uint32_t*>(smem + A_HI(buf) + off)     = h0;
            *reinterpret_cast<uint32_t*>(smem + A_HI(buf) + off + 4) = h1;
            *reinterpret_cast<uint32_t*>(smem + A_LO(buf) + off)     = l0;
            *reinterpret_cast<uint32_t*>(smem + A_LO(buf) + off + 4) = l1;
        }
    };
    auto loadB = [&](int kc0, int buf) {
#pragma unroll
        for (int i = 0; i < 5; i++) {
            const int idx = tid + 256 * i;     // 0..1279
            const int n = idx >> 2;
            const int seg = idx & 3;
            const int doff = n * A_STRIDE + seg * 16;
            const size_t goff = (size_t)n * K_PAD + kc0 + seg * 8;
            cp_async16(smem_base + B_HI(buf) + doff, g_bhi + goff);
            cp_async16(smem_base + B_LO(buf) + doff, g_blo + goff);
        }
        CP_COMMIT();
    };
    auto compute = [&](int buf) {
        const int abase = A_HI(buf) + (warp_m * 32 + lr) * A_STRIDE + lc * 4;
        const int bbase = B_HI(buf) + (warp_n * 80 + lr) * A_STRIDE + lc * 4;
        // preload all A fragments (hi+lo, both kk halves)
        uint32_t ah[2][2][4], al[2][2][4];
#pragma unroll
        for (int kk = 0; kk < 2; kk++)
#pragma unroll
            for (int mt = 0; mt < 2; mt++) {
                const int a0 = abase + mt * 16 * A_STRIDE + kk * 32;
                ah[kk][mt][0] = *reinterpret_cast<const uint32_t*>(smem + a0);
                ah[kk][mt][1] = *reinterpret_cast<const uint32_t*>(smem + a0 + 8 * A_STRIDE);
                ah[kk][mt][2] = *reinterpret_cast<const uint32_t*>(smem + a0 + 16);
                ah[kk][mt][3] = *reinterpret_cast<const uint32_t*>(smem + a0 + 8 * A_STRIDE + 16);
                const int a1 = a0 + A_BYTES;
                al[kk][mt][0] = *reinterpret_cast<const uint32_t*>(smem + a1);
                al[kk][mt][1] = *reinterpret_cast<const uint32_t*>(smem + a1 + 8 * A_STRIDE);
                al[kk][mt][2] = *reinterpret_cast<const uint32_t*>(smem + a1 + 16);
                al[kk][mt][3] = *reinterpret_cast<const uint32_t*>(smem + a1 + 8 * A_STRIDE + 16);
            }
        // term-outermost: 40 independent MMAs between accumulator reuses
#pragma unroll
        for (int t = 0; t < 3; t++) {
            const int bregion = (t == 1) ? B_BYTES : 0;   // t==1 -> B lo
#pragma unroll
            for (int kk = 0; kk < 2; kk++) {
#pragma unroll
                for (int nt = 0; nt < 10; nt++) {
                    const int b0 = bbase + bregion + nt * 8 * A_STRIDE + kk * 32;
                    const uint32_t bb0 = *reinterpret_cast<const uint32_t*>(smem + b0);
                    const uint32_t bb1 = *reinterpret_cast<const uint32_t*>(smem + b0 + 16);
#pragma unroll
                    for (int mt = 0; mt < 2; mt++) {
                        const uint32_t* af = (t == 2) ? al[kk][mt] : ah[kk][mt];
                        mma16816(acc[mt][nt], af, bb0, bb1);
                    }
                }
            }
        }
    };

    // ---- prologue: stage chunk 0 ----
    {
        float4 v[2];
        loadB(k_start, 0);
        loadA(k_start, v);
        stsA(0, v);
        CP_WAIT0();
        __syncthreads();
    }

    // ---- main loop: issue loads early, hide LDG/cp.async under compute ----
    for (int c = 0; c < NCHUNK; c++) {
        const int buf = c & 1;
        const bool has_next = (c + 1 < NCHUNK);
        float4 v[2];
        if (has_next) {
            loadB(k_start + (c + 1) * KC, buf ^ 1);   // async into other buffer
            loadA(k_start + (c + 1) * KC, v);          // LDG in flight during compute
        }
        compute(buf);
        if (has_next) {
            stsA(buf ^ 1, v);                          // consume LDG after compute
            CP_WAIT0();
        }
        __syncthreads();
    }

    // ---- epilogue: write split-K partials ----
    float* outp = g_partial + (size_t)s * BATCH * DIM;
#pragma unroll
    for (int mt = 0; mt < 2; mt++) {
        const int rbase = row0 + warp_m * 32 + mt * 16 + lr;
#pragma unroll
        for (int nt = 0; nt < 10; nt++) {
            const int col = warp_n * 80 + nt * 8 + 2 * lc;
            if (col < DIM) {
                outp[(size_t)rbase * DIM + col] = acc[mt][nt][0];
                if (col + 1 < DIM) outp[(size_t)rbase * DIM + col + 1] = acc[mt][nt][1];
                outp[(size_t)(rbase + 8) * DIM + col] = acc[mt][nt][2];
                if (col + 1 < DIM) outp[(size_t)(rbase + 8) * DIM + col + 1] = acc[mt][nt][3];
            }
        }
    }
}

// ---------------- reduce + L2 normalize (shfl-based) ----------------
__global__ __launch_bounds__(320) void reduce_norm_kernel(float* __restrict__ out)
{
    __shared__ float wsum[10];
    const int b = blockIdx.x;
    const int tid = threadIdx.x;

    float attr = 0.f;
    if (tid < DIM) {
#pragma unroll
        for (int s = 0; s < SPLITS; s++)
            attr += g_partial[((size_t)s * BATCH + b) * DIM + tid];
    }
    float sq = attr * attr;
#pragma unroll
    for (int off = 16; off > 0; off >>= 1)
        sq += __shfl_xor_sync(0xFFFFFFFFu, sq, off);
    if ((tid & 31) == 0) wsum[tid >> 5] = sq;
    __syncthreads();
    float total = 0.f;
#pragma unroll
    for (int w = 0; w < 10; w++) total += wsum[w];
    const float inv = 1.f / (sqrtf(total) + 1e-7f);
    if (tid < DIM) out[(size_t)b * DIM + tid] = attr * inv;
}

extern "C" void kernel_launch(void* const* d_in, const int* in_sizes, int n_in,
                              void* d_out, int out_size)
{
    const float* labels = (const float*)d_in[0];   // (1024, 50000)
    const float* weight = (const float*)d_in[1];   // (50000, 300)
    float* out = (float*)d_out;                    // (1024, 300)

    cudaFuncSetAttribute(gemm_kernel, cudaFuncAttributeMaxDynamicSharedMemorySize,
                         SMEM_TOTAL);

    prep_kernel<<<dim3(K_PAD / 32, BN / 32), 256>>>(weight);
    gemm_kernel<<<dim3(BATCH / BM, SPLITS), 256, SMEM_TOTAL>>>(labels);
    reduce_norm_kernel<<<BATCH, 320>>>(out);
}

// round 9
// speedup vs baseline: 3.3466x; 1.0176x over previous
#include <cuda_runtime.h>
#include <cuda_bf16.h>
#include <cstdint>

#define BATCH 1024
#define VOCAB 50000
#define DIM   300

#define BM      64
#define BN      304             // 38 n8-tiles, covers DIM=300
#define BN_ALLOC 320            // allocation/prep padding
#define KC      32
#define SPLITS  9
#define SEG     5568            // SPLITS*SEG = 50112 >= VOCAB, mult of KC
#define K_PAD   50112
#define NCHUNK  (SEG / KC)      // 174

// -------- static device scratch (no allocations allowed) --------
__device__ __nv_bfloat16 g_bhi[(size_t)BN_ALLOC * K_PAD];   // weight hi, [n][k]
__device__ __nv_bfloat16 g_blo[(size_t)BN_ALLOC * K_PAD];   // weight lo, [n][k]
__device__ float g_partial[(size_t)SPLITS * BATCH * DIM];

// smem layout. Row stride 40 bf16 = 80B (conflict-free frags).
#define A_STRIDE 80
#define A_BYTES  (64 * A_STRIDE)        // 5120
#define B_BYTES  (BN * A_STRIDE)        // 24320
#define BUF_BYTES (2 * A_BYTES + 2 * B_BYTES)   // 58880
#define A_HI(b) ((b) * BUF_BYTES + 0)
#define A_LO(b) ((b) * BUF_BYTES + A_BYTES)
#define B_HI(b) ((b) * BUF_BYTES + 2 * A_BYTES)
#define B_LO(b) ((b) * BUF_BYTES + 2 * A_BYTES + B_BYTES)
#define SMEM_TOTAL (2 * BUF_BYTES)      // 117760

__device__ __forceinline__ uint32_t smem_u32(const void* p) {
    uint32_t a;
    asm("{ .reg .u64 t; cvta.to.shared.u64 t, %1; cvt.u32.u64 %0, t; }"
        : "=r"(a) : "l"(p));
    return a;
}
__device__ __forceinline__ void cp_async16(uint32_t dst, const void* src) {
    asm volatile("{ .reg .u64 g; cvta.to.global.u64 g, %1; "
                 "cp.async.ca.shared.global [%0], [g], 16; }"
                 :: "r"(dst), "l"(src) : "memory");
}
#define CP_COMMIT() asm volatile("cp.async.commit_group;" ::: "memory")
#define CP_WAIT0()  asm volatile("cp.async.wait_group 0;" ::: "memory")

__device__ __forceinline__ void mma16816(float* d, const uint32_t* a,
                                         uint32_t b0, uint32_t b1) {
    asm volatile("mma.sync.aligned.m16n8k16.row.col.f32.bf16.bf16.f32 "
                 "{%0,%1,%2,%3}, {%4,%5,%6,%7}, {%8,%9}, {%0,%1,%2,%3};"
                 : "+f"(d[0]), "+f"(d[1]), "+f"(d[2]), "+f"(d[3])
                 : "r"(a[0]), "r"(a[1]), "r"(a[2]), "r"(a[3]), "r"(b0), "r"(b1));
}

// split (x,y) into packed bf16x2 hi + lo (low half = x)
__device__ __forceinline__ void cvt_split2(float x, float y, uint32_t& h, uint32_t& l) {
    uint32_t hh;
    asm("cvt.rn.bf16x2.f32 %0, %1, %2;" : "=r"(hh) : "f"(y), "f"(x));
    float hx = __uint_as_float(hh << 16);
    float hy = __uint_as_float(hh & 0xFFFF0000u);
    float lx = x - hx, ly = y - hy;
    asm("cvt.rn.bf16x2.f32 %0, %1, %2;" : "=r"(l) : "f"(ly), "f"(lx));
    h = hh;
}

// ---------------- prep: weight f32 [K][300] -> bf16 hi/lo [320][K_PAD] ----------------
// 64k x 32n tile per block; each thread: 8 loads, 8 hi+lo converts, 2x uint2 stores each
__global__ __launch_bounds__(256) void prep_kernel(const float* __restrict__ weight)
{
    __shared__ float t[64][33];
    const int k0 = blockIdx.x * 64;
    const int n0 = blockIdx.y * 32;
    const int tx = threadIdx.x & 31;
    const int ty = threadIdx.x >> 5;     // 0..7
#pragma unroll
    for (int i = 0; i < 8; i++) {
        const int k = k0 + ty + i * 8;
        const int n = n0 + tx;
        t[ty + i * 8][tx] = (k < VOCAB && n < DIM) ? weight[(size_t)k * DIM + n] : 0.f;
    }
    __syncthreads();
    const int nl = threadIdx.x >> 3;           // 0..31
    const int kg = (threadIdx.x & 7) * 8;      // 0..56
    __nv_bfloat16 harr[8], larr[8];
#pragma unroll
    for (int j = 0; j < 8; j++) {
        const float v = t[kg + j][nl];
        const __nv_bfloat16 h = __float2bfloat16_rn(v);
        harr[j] = h;
        larr[j] = __float2bfloat16_rn(v - __bfloat162float(h));
    }
    const size_t off = (size_t)(n0 + nl) * K_PAD + k0 + kg;
    *reinterpret_cast<uint2*>(g_bhi + off)     = *reinterpret_cast<uint2*>(harr);
    *reinterpret_cast<uint2*>(g_bhi + off + 4) = *reinterpret_cast<uint2*>(harr + 4);
    *reinterpret_cast<uint2*>(g_blo + off)     = *reinterpret_cast<uint2*>(larr);
    *reinterpret_cast<uint2*>(g_blo + off + 4) = *reinterpret_cast<uint2*>(larr + 4);
}

// ---------------- GEMM: HMMA bf16 3-term split, split-K, 8x19-tile balance -------------
__global__ __launch_bounds__(256, 1) void gemm_kernel(const float* __restrict__ labels)
{
    extern __shared__ char smem[];
    const uint32_t smem_base = smem_u32(smem);

    const int tid = threadIdx.x;
    const int wid = tid >> 5;
    const int lane = tid & 31;
    const int lr = lane >> 2;            // 0..7
    const int lc = lane & 3;             // 0..3
    const int m_strip = wid & 3;         // 4 m16 strips
    const int nt0 = (wid >> 2) * 19;     // n-tile base: 0 or 19

    const int row0 = blockIdx.x * BM;
    const int s = blockIdx.y;
    const int k_start = s * SEG;

    // A f32 staging indices
    const int arow = tid >> 3;           // 0..31 (rows r and r+32)
    const int af4 = tid & 7;             // float4 col 0..7

    float acc[19][4];
#pragma unroll
    for (int nt = 0; nt < 19; nt++)
#pragma unroll
        for (int i = 0; i < 4; i++) acc[nt][i] = 0.f;

    auto loadA = [&](int kc0, float4* v) {
#pragma unroll
        for (int i = 0; i < 2; i++) {
            const int r = row0 + arow + i * 32;
            const int k = kc0 + af4 * 4;
            const float* src = labels + (size_t)r * VOCAB + k;
            if (k + 3 < VOCAB) {
                v[i] = *reinterpret_cast<const float4*>(src);
            } else {
                v[i].x = (k     < VOCAB) ? src[0] : 0.f;
                v[i].y = (k + 1 < VOCAB) ? src[1] : 0.f;
                v[i].z = (k + 2 < VOCAB) ? src[2] : 0.f;
                v[i].w = (k + 3 < VOCAB) ? src[3] : 0.f;
            }
        }
    };
    auto stsA = [&](int buf, const float4* v) {
#pragma unroll
        for (int i = 0; i < 2; i++) {
            uint32_t h0, l0, h1, l1;
            cvt_split2(v[i].x, v[i].y, h0, l0);
            cvt_split2(v[i].z, v[i].w, h1, l1);
            const int off = (arow + i * 32) * A_STRIDE + af4 * 8;
            *reinterpret_cast<uint32_t*>(smem + A_HI(buf) + off)     = h0;
            *reinterpret_cast<uint32_t*>(smem + A_HI(buf) + off + 4) = h1;
            *reinterpret_cast<uint32_t*>(smem + A_LO(buf) + off)     = l0;
            *reinterpret_cast<uint32_t*>(smem + A_LO(buf) + off + 4) = l1;
        }
    };
    auto loadB = [&](int kc0, int buf) {
#pragma unroll
        for (int i = 0; i < 5; i++) {
            const int idx = tid + 256 * i;     // 0..1279, valid < 1216
            if (idx < BN * 4) {
                const int n = idx >> 2;
                const int seg = idx & 3;
                const int doff = n * A_STRIDE + seg * 16;
                const size_t goff = (size_t)n * K_PAD + kc0 + seg * 8;
                cp_async16(smem_base + B_HI(buf) + doff, g_bhi + goff);
                cp_async16(smem_base + B_LO(buf) + doff, g_blo + goff);
            }
        }
        CP_COMMIT();
    };
    auto compute = [&](int buf) {
        const int abase = A_HI(buf) + (m_strip * 16 + lr) * A_STRIDE + lc * 4;
        const int bbase = B_HI(buf) + (nt0 * 8 + lr) * A_STRIDE + lc * 4;
        // preload A fragments for this m-strip (hi+lo, both kk halves)
        uint32_t ah[2][4], al[2][4];
#pragma unroll
        for (int kk = 0; kk < 2; kk++) {
            const int a0 = abase + kk * 32;
            ah[kk][0] = *reinterpret_cast<const uint32_t*>(smem + a0);
            ah[kk][1] = *reinterpret_cast<const uint32_t*>(smem + a0 + 8 * A_STRIDE);
            ah[kk][2] = *reinterpret_cast<const uint32_t*>(smem + a0 + 16);
            ah[kk][3] = *reinterpret_cast<const uint32_t*>(smem + a0 + 8 * A_STRIDE + 16);
            const int a1 = a0 + A_BYTES;
            al[kk][0] = *reinterpret_cast<const uint32_t*>(smem + a1);
            al[kk][1] = *reinterpret_cast<const uint32_t*>(smem + a1 + 8 * A_STRIDE);
            al[kk][2] = *reinterpret_cast<const uint32_t*>(smem + a1 + 16);
            al[kk][3] = *reinterpret_cast<const uint32_t*>(smem + a1 + 8 * A_STRIDE + 16);
        }
        // term-outermost: 19 independent accumulators between reuses
#pragma unroll
        for (int t = 0; t < 3; t++) {
            const int bregion = (t == 1) ? B_BYTES : 0;   // t==1 -> B lo
#pragma unroll
            for (int kk = 0; kk < 2; kk++) {
                const uint32_t* af = (t == 2) ? al[kk] : ah[kk];
#pragma unroll
                for (int nt = 0; nt < 19; nt++) {
                    const int b0 = bbase + bregion + nt * 8 * A_STRIDE + kk * 32;
                    const uint32_t bb0 = *reinterpret_cast<const uint32_t*>(smem + b0);
                    const uint32_t bb1 = *reinterpret_cast<const uint32_t*>(smem + b0 + 16);
                    mma16816(acc[nt], af, bb0, bb1);
                }
            }
        }
    };

    // ---- prologue: stage chunk 0 ----
    {
        float4 v[2];
        loadB(k_start, 0);
        loadA(k_start, v);
        stsA(0, v);
        CP_WAIT0();
        __syncthreads();
    }

    // ---- main loop: issue loads early, hide LDG/cp.async under compute ----
    for (int c = 0; c < NCHUNK; c++) {
        const int buf = c & 1;
        const bool has_next = (c + 1 < NCHUNK);
        float4 v[2];
        if (has_next) {
            loadB(k_start + (c + 1) * KC, buf ^ 1);   // async into other buffer
            loadA(k_start + (c + 1) * KC, v);          // LDG in flight during compute
        }
        compute(buf);
        if (has_next) {
            stsA(buf ^ 1, v);                          // consume LDG after compute
            CP_WAIT0();
        }
        __syncthreads();
    }

    // ---- epilogue: write split-K partials ----
    float* outp = g_partial + (size_t)s * BATCH * DIM;
    const int r0 = row0 + m_strip * 16 + lr;
#pragma unroll
    for (int nt = 0; nt < 19; nt++) {
        const int col = (nt0 + nt) * 8 + 2 * lc;
        if (col < DIM) {
            outp[(size_t)r0 * DIM + col] = acc[nt][0];
            if (col + 1 < DIM) outp[(size_t)r0 * DIM + col + 1] = acc[nt][1];
            outp[(size_t)(r0 + 8) * DIM + col] = acc[nt][2];
            if (col + 1 < DIM) outp[(size_t)(r0 + 8) * DIM + col + 1] = acc[nt][3];
        }
    }
}

// ---------------- reduce + L2 normalize (shfl-based) ----------------
__global__ __launch_bounds__(320) void reduce_norm_kernel(float* __restrict__ out)
{
    __shared__ float wsum[10];
    const int b = blockIdx.x;
    const int tid = threadIdx.x;

    float attr = 0.f;
    if (tid < DIM) {
#pragma unroll
        for (int s = 0; s < SPLITS; s++)
            attr += g_partial[((size_t)s * BATCH + b) * DIM + tid];
    }
    float sq = attr * attr;
#pragma unroll
    for (int off = 16; off > 0; off >>= 1)
        sq += __shfl_xor_sync(0xFFFFFFFFu, sq, off);
    if ((tid & 31) == 0) wsum[tid >> 5] = sq;
    __syncthreads();
    float total = 0.f;
#pragma unroll
    for (int w = 0; w < 10; w++) total += wsum[w];
    const float inv = 1.f / (sqrtf(total) + 1e-7f);
    if (tid < DIM) out[(size_t)b * DIM + tid] = attr * inv;
}

extern "C" void kernel_launch(void* const* d_in, const int* in_sizes, int n_in,
                              void* d_out, int out_size)
{
    const float* labels = (const float*)d_in[0];   // (1024, 50000)
    const float* weight = (const float*)d_in[1];   // (50000, 300)
    float* out = (float*)d_out;                    // (1024, 300)

    cudaFuncSetAttribute(gemm_kernel, cudaFuncAttributeMaxDynamicSharedMemorySize,
                         SMEM_TOTAL);

    prep_kernel<<<dim3(K_PAD / 64, BN_ALLOC / 32), 256>>>(weight);
    gemm_kernel<<<dim3(BATCH / BM, SPLITS), 256, SMEM_TOTAL>>>(labels);
    reduce_norm_kernel<<<BATCH, 320>>>(out);
}